// round 2
// baseline (speedup 1.0000x reference)
#include <cuda_runtime.h>
#include <cuda_bf16.h>
#include <math.h>

#define BIGF 1000000000.0f
#define RING 64

// Scratch: cost matrix in anti-diagonal layout Cdiag[b][k][i], k = i+j in [0,2046],
// padded to 2048 diagonals. 32 * 2048 * 1024 floats = 256 MB.
static __device__ __align__(256) float g_Cdiag[67108864];
static __device__ float g_n1[32 * 1024];
static __device__ float g_n2[32 * 1024];

// ---------------------------------------------------------------------------
// Kernel 0: row squared norms. grid (128, 32, 2), 256 threads, one warp per row.
// ---------------------------------------------------------------------------
__global__ __launch_bounds__(256) void norms_kernel(const float* __restrict__ s1,
                                                    const float* __restrict__ s2) {
    int b = blockIdx.y;
    const float* s = blockIdx.z ? s2 : s1;
    float* o = blockIdx.z ? g_n2 : g_n1;
    int lane = threadIdx.x & 31;
    int wid = threadIdx.x >> 5;  // 8 warps
    int r = blockIdx.x * 8 + wid;
    const float4* p = (const float4*)(s + ((size_t)b * 1024 + r) * 128);
    float4 v = p[lane];  // 128 floats = 32 float4 per row, one per lane
    float acc = v.x * v.x + v.y * v.y + v.z * v.z + v.w * v.w;
#pragma unroll
    for (int off = 16; off; off >>= 1)
        acc += __shfl_xor_sync(0xffffffffu, acc, off);
    if (lane == 0) o[b * 1024 + r] = acc;
}

// ---------------------------------------------------------------------------
// Kernel 1: cost matrix. grid (16, 16, 32) = (j-tile, i-tile, batch).
// 256 threads = 16x16, each computes a 4x4 register tile over K=128 (4 chunks of 32).
// Epilogue: C = sqrt(max(n1 + n2 - 2*dot, 0)), staged through shared memory and
// written out in anti-diagonal-major layout (coalesced diagonal segments).
// ---------------------------------------------------------------------------
__global__ __launch_bounds__(256) void cost_kernel(const float* __restrict__ s1,
                                                   const float* __restrict__ s2) {
    __shared__ float smem[4352];        // asT[32][68] + bsT[32][68]; reused as Ss[64][66]
    float* asT = smem;                  // transposed A chunk: asT[k][i], pitch 68
    float* bsT = smem + 32 * 68;        // transposed B chunk: bsT[k][j], pitch 68

    int b = blockIdx.z;
    int i0 = blockIdx.y * 64;
    int j0 = blockIdx.x * 64;
    int tid = threadIdx.x;
    int tx = tid & 15;
    int ty = tid >> 4;

    const float* A = s1 + ((size_t)b * 1024 + i0) * 128;
    const float* B = s2 + ((size_t)b * 1024 + j0) * 128;

    float acc[4][4];
#pragma unroll
    for (int u = 0; u < 4; u++)
#pragma unroll
        for (int v = 0; v < 4; v++) acc[u][v] = 0.0f;

    for (int kc0 = 0; kc0 < 128; kc0 += 32) {
        __syncthreads();
#pragma unroll
        for (int it = 0; it < 8; it++) {
            int e = tid + it * 256;      // 2048 elements = 64 rows x 32 cols
            int r = e >> 5;
            int c = e & 31;
            asT[c * 68 + r] = A[r * 128 + kc0 + c];
            bsT[c * 68 + r] = B[r * 128 + kc0 + c];
        }
        __syncthreads();
#pragma unroll
        for (int k = 0; k < 32; k++) {
            float4 a4 = *(const float4*)&asT[k * 68 + ty * 4];
            float4 b4 = *(const float4*)&bsT[k * 68 + tx * 4];
            float av[4] = {a4.x, a4.y, a4.z, a4.w};
            float bv[4] = {b4.x, b4.y, b4.z, b4.w};
#pragma unroll
            for (int u = 0; u < 4; u++)
#pragma unroll
                for (int v = 0; v < 4; v++) acc[u][v] += av[u] * bv[v];
        }
    }
    __syncthreads();

    // Epilogue: distances into staging buffer Ss[64][66] (pitch 66 makes the
    // diagonal read stride 65 -> conflict-free).
    float* Ss = smem;
#pragma unroll
    for (int u = 0; u < 4; u++) {
        float n1 = g_n1[b * 1024 + i0 + ty * 4 + u];
#pragma unroll
        for (int v = 0; v < 4; v++) {
            float n2 = g_n2[b * 1024 + j0 + tx * 4 + v];
            float d2 = n1 + n2 - 2.0f * acc[u][v];
            Ss[(ty * 4 + u) * 66 + tx * 4 + v] = sqrtf(fmaxf(d2, 0.0f));
        }
    }
    __syncthreads();

    // Diagonal write-out: 127 local diagonals d = li + lj, global k = i0 + j0 + d.
    int lane = tid & 31;
    int w8 = tid >> 5;  // 8 warps
    for (int d = w8; d < 127; d += 8) {
        int lo = d > 63 ? d - 63 : 0;
        int hi = d < 63 ? d : 63;
        size_t base = ((size_t)b * 2048 + (size_t)(i0 + j0 + d)) * 1024 + i0;
        int li = lo + lane;
        if (li <= hi) g_Cdiag[base + li] = Ss[li * 66 + (d - li)];
        li += 32;
        if (li <= hi) g_Cdiag[base + li] = Ss[li * 66 + (d - li)];
    }
}

// ---------------------------------------------------------------------------
// Kernel 2: DTW wavefront, barrier-free skewed warp pipeline.
// One CTA of 256 threads per batch; thread t owns rows 4t+1..4t+4.
// Per anti-diagonal k: within-thread vertical deps are a register chain,
// warp-internal boundary via one shfl_up, inter-warp boundaries via a 64-slot
// shared ring with sentinel-based produce/consume (no __syncthreads in loop).
// Loop runs 2048 iterations (k=2..2049); answer is prev2[3] of thread 255.
// ---------------------------------------------------------------------------
__global__ __launch_bounds__(256) void dtw_kernel(float* __restrict__ out) {
    int b = blockIdx.x;
    int t = threadIdx.x;
    int lane = t & 31;
    int w = t >> 5;  // 8 warps

    __shared__ volatile float ring[7][RING];
    for (int s = t; s < 7 * RING; s += 256)
        (&ring[0][0])[s] = -1.0f;  // sentinel = "empty"
    __syncthreads();

    const float4* Cb4 = (const float4*)(g_Cdiag + (size_t)b * 2048 * 1024);
    // diag kc, thread t -> Cb4[kc*256 + t] = C rows 4t..4t+3 on that diagonal

    float prev[4], prev2[4];
#pragma unroll
    for (int r = 0; r < 4; r++) { prev[r] = BIGF; prev2[r] = BIGF; }

    float4 cb[8];
#pragma unroll
    for (int q = 0; q < 8; q++) cb[q] = Cb4[q * 256 + t];

    volatile float* rd = (w > 0) ? &ring[w - 1][0] : &ring[0][0];
    volatile float* wr = (w < 7) ? &ring[w][0] : &ring[0][0];
    bool is_prod = (lane == 31) && (w < 7);
    bool is_cons = (lane == 0) && (w > 0);

    int i0 = 4 * t + 1;  // first DP row owned by this thread

    for (int kb = 0; kb < 256; ++kb) {
#pragma unroll
        for (int u = 0; u < 8; ++u) {
            int k = 2 + kb * 8 + u;          // k = 2..2049
            float4 cv = cb[u];
            int pf = (k - 2) + 8;
            if (pf > 2047) pf = 2047;
            cb[u] = Cb4[(size_t)pf * 256 + t];

            float nm0 = fminf(prev[0], prev2[0]);
            float nm1 = fminf(prev[1], prev2[1]);
            float nm2 = fminf(prev[2], prev2[2]);
            float nm3 = fminf(prev[3], prev2[3]);

            float handoff = __shfl_up_sync(0xffffffffu, nm3, 1);

            // producer: publish boundary value for the next warp (slot must be empty)
            if (is_prod) {
                volatile float* p = &wr[k & (RING - 1)];
                while (*p >= 0.0f) { }
                *p = nm3;
            }

            float up0 = handoff;
            if (lane == 0) {
                if (w == 0) {
                    up0 = (k == 2) ? 0.0f : BIGF;   // DP row 0: D[0][0]=0, else inf
                } else {
                    volatile float* p = &rd[k & (RING - 1)];
                    float v = *p;
                    while (v < 0.0f) v = *p;
                    *p = -1.0f;                      // mark consumed
                    up0 = v;
                }
            }

            float c0 = cv.x + fminf(prev[0], up0);
            float c1 = cv.y + fminf(prev[1], nm0);
            float c2 = cv.z + fminf(prev[2], nm1);
            float c3 = cv.w + fminf(prev[3], nm2);

            bool v0 = (k >= i0 + 1) && (k <= i0 + 1024);
            bool v1 = (k >= i0 + 2) && (k <= i0 + 1025);
            bool v2 = (k >= i0 + 3) && (k <= i0 + 1026);
            bool v3 = (k >= i0 + 4) && (k <= i0 + 1027);

            prev2[0] = prev[0]; prev[0] = v0 ? c0 : BIGF;
            prev2[1] = prev[1]; prev[1] = v1 ? c1 : BIGF;
            prev2[2] = prev[2]; prev[2] = v2 ? c2 : BIGF;
            prev2[3] = prev[3]; prev[3] = v3 ? c3 : BIGF;
        }
    }

    if (t == 255) {
        // After the k=2049 iteration, prev2[3] = D[1024][1024] (from k=2048).
        float dist = prev2[3] * (1.0f / 2048.0f);
        out[b] = 1.0f / (1.0f + dist);
    }
}

// ---------------------------------------------------------------------------
extern "C" void kernel_launch(void* const* d_in, const int* in_sizes, int n_in,
                              void* d_out, int out_size) {
    const float* seq1 = (const float*)d_in[0];
    const float* seq2 = (const float*)d_in[1];
    // d_in[2] = scale_weights (1 elem): softmax of a single weight is exactly 1.0.
    float* out = (float*)d_out;

    dim3 gN(128, 32, 2);
    norms_kernel<<<gN, 256>>>(seq1, seq2);

    dim3 gC(16, 16, 32);
    cost_kernel<<<gC, 256>>>(seq1, seq2);

    dtw_kernel<<<32, 256>>>(out);
}

// round 3
// speedup vs baseline: 1.5543x; 1.5543x over previous
#include <cuda_runtime.h>
#include <cuda_bf16.h>
#include <math.h>

#define BIGF 1000000000.0f

// Scratch: cost matrix in anti-diagonal layout Cdiag[b][k][i], k = i+j in [0,2046],
// padded to 2048 diagonals. 32 * 2048 * 1024 floats = 256 MB.
static __device__ __align__(256) float g_Cdiag[67108864];
static __device__ float g_n1[32 * 1024];
static __device__ float g_n2[32 * 1024];

// ---------------------------------------------------------------------------
// Kernel 0: row squared norms. grid (128, 32, 2), 256 threads, one warp per row.
// ---------------------------------------------------------------------------
__global__ __launch_bounds__(256) void norms_kernel(const float* __restrict__ s1,
                                                    const float* __restrict__ s2) {
    int b = blockIdx.y;
    const float* s = blockIdx.z ? s2 : s1;
    float* o = blockIdx.z ? g_n2 : g_n1;
    int lane = threadIdx.x & 31;
    int wid = threadIdx.x >> 5;  // 8 warps
    int r = blockIdx.x * 8 + wid;
    const float4* p = (const float4*)(s + ((size_t)b * 1024 + r) * 128);
    float4 v = p[lane];  // 128 floats = 32 float4 per row, one per lane
    float acc = v.x * v.x + v.y * v.y + v.z * v.z + v.w * v.w;
#pragma unroll
    for (int off = 16; off; off >>= 1)
        acc += __shfl_xor_sync(0xffffffffu, acc, off);
    if (lane == 0) o[b * 1024 + r] = acc;
}

// ---------------------------------------------------------------------------
// Kernel 1: cost matrix. grid (16, 16, 32) = (j-tile, i-tile, batch).
// 256 threads = 16x16, each computes a 4x4 register tile over K=128 (4 chunks of 32).
// Epilogue: C = sqrt(max(n1 + n2 - 2*dot, 0)), staged through shared memory and
// written out in anti-diagonal-major layout (coalesced diagonal segments).
// ---------------------------------------------------------------------------
__global__ __launch_bounds__(256) void cost_kernel(const float* __restrict__ s1,
                                                   const float* __restrict__ s2) {
    __shared__ float smem[4352];        // asT[32][68] + bsT[32][68]; reused as Ss[64][66]
    float* asT = smem;                  // transposed A chunk: asT[k][i], pitch 68
    float* bsT = smem + 32 * 68;        // transposed B chunk: bsT[k][j], pitch 68

    int b = blockIdx.z;
    int i0 = blockIdx.y * 64;
    int j0 = blockIdx.x * 64;
    int tid = threadIdx.x;
    int tx = tid & 15;
    int ty = tid >> 4;

    const float* A = s1 + ((size_t)b * 1024 + i0) * 128;
    const float* B = s2 + ((size_t)b * 1024 + j0) * 128;

    float acc[4][4];
#pragma unroll
    for (int u = 0; u < 4; u++)
#pragma unroll
        for (int v = 0; v < 4; v++) acc[u][v] = 0.0f;

    for (int kc0 = 0; kc0 < 128; kc0 += 32) {
        __syncthreads();
#pragma unroll
        for (int it = 0; it < 8; it++) {
            int e = tid + it * 256;      // 2048 elements = 64 rows x 32 cols
            int r = e >> 5;
            int c = e & 31;
            asT[c * 68 + r] = A[r * 128 + kc0 + c];
            bsT[c * 68 + r] = B[r * 128 + kc0 + c];
        }
        __syncthreads();
#pragma unroll
        for (int k = 0; k < 32; k++) {
            float4 a4 = *(const float4*)&asT[k * 68 + ty * 4];
            float4 b4 = *(const float4*)&bsT[k * 68 + tx * 4];
            float av[4] = {a4.x, a4.y, a4.z, a4.w};
            float bv[4] = {b4.x, b4.y, b4.z, b4.w};
#pragma unroll
            for (int u = 0; u < 4; u++)
#pragma unroll
                for (int v = 0; v < 4; v++) acc[u][v] += av[u] * bv[v];
        }
    }
    __syncthreads();

    // Epilogue: distances into staging buffer Ss[64][66] (pitch 66 makes the
    // diagonal read stride 65 -> conflict-free).
    float* Ss = smem;
#pragma unroll
    for (int u = 0; u < 4; u++) {
        float n1 = g_n1[b * 1024 + i0 + ty * 4 + u];
#pragma unroll
        for (int v = 0; v < 4; v++) {
            float n2 = g_n2[b * 1024 + j0 + tx * 4 + v];
            float d2 = n1 + n2 - 2.0f * acc[u][v];
            Ss[(ty * 4 + u) * 66 + tx * 4 + v] = sqrtf(fmaxf(d2, 0.0f));
        }
    }
    __syncthreads();

    // Diagonal write-out: 127 local diagonals d = li + lj, global k = i0 + j0 + d.
    int lane = tid & 31;
    int w8 = tid >> 5;  // 8 warps
    for (int d = w8; d < 127; d += 8) {
        int lo = d > 63 ? d - 63 : 0;
        int hi = d < 63 ? d : 63;
        size_t base = ((size_t)b * 2048 + (size_t)(i0 + j0 + d)) * 1024 + i0;
        int li = lo + lane;
        if (li <= hi) g_Cdiag[base + li] = Ss[li * 66 + (d - li)];
        li += 32;
        if (li <= hi) g_Cdiag[base + li] = Ss[li * 66 + (d - li)];
    }
}

// ---------------------------------------------------------------------------
// Kernel 2: DTW wavefront. One CTA of 256 threads per batch; thread t owns DP
// rows 4t+1..4t+4 as a register chain. Per anti-diagonal k: 4 fmin for the
// neighbor mins, one shfl_up for the warp-internal boundary, a double-buffered
// 8-slot shared edge array + ONE __syncthreads for warp boundaries. The edge
// value (nm3) depends only on pre-barrier registers, so the barrier-to-barrier
// critical path is short. 16-deep float4 prefetch ring hides cost-read latency.
// Loop runs k=2..2049; answer is prev2[3] of thread 255 after the last iter.
// ---------------------------------------------------------------------------
__global__ __launch_bounds__(256) void dtw_kernel(float* __restrict__ out) {
    int b = blockIdx.x;
    int t = threadIdx.x;
    int lane = t & 31;
    int w = t >> 5;  // 8 warps

    __shared__ float edge[2][9];

    const float4* Cb4 = (const float4*)(g_Cdiag + (size_t)b * 2048 * 1024);
    // diag kc, thread t -> Cb4[kc*256 + t] = C rows 4t..4t+3 on that diagonal

    float prev[4], prev2[4];
#pragma unroll
    for (int r = 0; r < 4; r++) { prev[r] = BIGF; prev2[r] = BIGF; }

    float4 cb[16];
#pragma unroll
    for (int q = 0; q < 16; q++) cb[q] = Cb4[q * 256 + t];

    int i0 = 4 * t + 1;  // first DP row owned by this thread

    for (int kb = 0; kb < 128; ++kb) {
#pragma unroll
        for (int u = 0; u < 16; ++u) {
            int k = 2 + kb * 16 + u;          // k = 2..2049
            float4 cv = cb[u];
            int pf = (k - 2) + 16;
            if (pf > 2047) pf = 2047;
            cb[u] = Cb4[(size_t)pf * 256 + t];

            float nm0 = fminf(prev[0], prev2[0]);
            float nm1 = fminf(prev[1], prev2[1]);
            float nm2 = fminf(prev[2], prev2[2]);
            float nm3 = fminf(prev[3], prev2[3]);

            // publish warp-boundary value for the next warp (pre-barrier data only)
            if (lane == 31 && w < 7) edge[k & 1][w + 1] = nm3;
            __syncthreads();

            float handoff = __shfl_up_sync(0xffffffffu, nm3, 1);  // from row 4t (thread t-1)
            float up0 = handoff;
            if (lane == 0)
                up0 = (w == 0) ? ((k == 2) ? 0.0f : BIGF) : edge[k & 1][w];

            float c0 = cv.x + fminf(prev[0], up0);
            float c1 = cv.y + fminf(prev[1], nm0);
            float c2 = cv.z + fminf(prev[2], nm1);
            float c3 = cv.w + fminf(prev[3], nm2);

            bool v0 = (k >= i0 + 1) && (k <= i0 + 1024);
            bool v1 = (k >= i0 + 2) && (k <= i0 + 1025);
            bool v2 = (k >= i0 + 3) && (k <= i0 + 1026);
            bool v3 = (k >= i0 + 4) && (k <= i0 + 1027);

            prev2[0] = prev[0]; prev[0] = v0 ? c0 : BIGF;
            prev2[1] = prev[1]; prev[1] = v1 ? c1 : BIGF;
            prev2[2] = prev[2]; prev[2] = v2 ? c2 : BIGF;
            prev2[3] = prev[3]; prev[3] = v3 ? c3 : BIGF;
        }
    }

    if (t == 255) {
        // After the k=2049 iteration, prev2[3] = D[1024][1024] (from k=2048).
        // softmax over a single weight == 1 exactly.
        float dist = prev2[3] * (1.0f / 2048.0f);
        out[b] = 1.0f / (1.0f + dist);
    }
}

// ---------------------------------------------------------------------------
extern "C" void kernel_launch(void* const* d_in, const int* in_sizes, int n_in,
                              void* d_out, int out_size) {
    const float* seq1 = (const float*)d_in[0];
    const float* seq2 = (const float*)d_in[1];
    // d_in[2] = scale_weights (1 elem): softmax of a single weight is exactly 1.0.
    float* out = (float*)d_out;

    dim3 gN(128, 32, 2);
    norms_kernel<<<gN, 256>>>(seq1, seq2);

    dim3 gC(16, 16, 32);
    cost_kernel<<<gC, 256>>>(seq1, seq2);

    dtw_kernel<<<32, 256>>>(out);
}

// round 4
// speedup vs baseline: 1.6475x; 1.0600x over previous
#include <cuda_runtime.h>
#include <cuda_bf16.h>
#include <math.h>

#define BIGF 1000000000.0f

// Scratch: cost matrix in anti-diagonal layout Cdiag[b][kc][i], kc = i+j in [0,2046],
// padded to 2048 diagonals. 32 * 2048 * 1024 floats = 256 MB.
static __device__ __align__(256) float g_Cdiag[67108864];
static __device__ float g_n1[32 * 1024];
static __device__ float g_n2[32 * 1024];

// ---------------------------------------------------------------------------
// Kernel 0: row squared norms. grid (128, 32, 2), 256 threads, one warp per row.
// ---------------------------------------------------------------------------
__global__ __launch_bounds__(256) void norms_kernel(const float* __restrict__ s1,
                                                    const float* __restrict__ s2) {
    int b = blockIdx.y;
    const float* s = blockIdx.z ? s2 : s1;
    float* o = blockIdx.z ? g_n2 : g_n1;
    int lane = threadIdx.x & 31;
    int wid = threadIdx.x >> 5;  // 8 warps
    int r = blockIdx.x * 8 + wid;
    const float4* p = (const float4*)(s + ((size_t)b * 1024 + r) * 128);
    float4 v = p[lane];
    float acc = v.x * v.x + v.y * v.y + v.z * v.z + v.w * v.w;
#pragma unroll
    for (int off = 16; off; off >>= 1)
        acc += __shfl_xor_sync(0xffffffffu, acc, off);
    if (lane == 0) o[b * 1024 + r] = acc;
}

// ---------------------------------------------------------------------------
// Kernel 1: cost matrix via packed f32x2 FFMA (2 fp32 FMA per instruction).
// grid (16, 8, 32) = (j-tile, i-tile, batch). Tile = 128(i) x 64(j), 256 thr,
// 8x4 per thread. A chunk stored transposed asT[k][i] (LDS.64 -> (a_i,a_i+1)
// row pair). B chunk stored DUPLICATED + swizzled bsD[k][(j&3)*16+(j>>2)]x2
// (LDS.64 -> (b_j,b_j) splat, conflict-free: 16 lanes hit 16 distinct banks).
// Epilogue: sqrt(max(n1+n2-2dot,0)), staged in shared, written out in
// anti-diagonal-major layout (coalesced diagonal segments).
// ---------------------------------------------------------------------------
__global__ __launch_bounds__(256) void cost_kernel(const float* __restrict__ s1,
                                                   const float* __restrict__ s2) {
    __shared__ float smem[8448];   // asT[32][132] + bsD[32][132]; reused as Ss[128][66]
    float* asT = smem;
    float* bsD = smem + 4224;

    int b = blockIdx.z;
    int i0 = blockIdx.y * 128;
    int j0 = blockIdx.x * 64;
    int tid = threadIdx.x;
    int tx = tid & 15;   // j groups of 4
    int ty = tid >> 4;   // i groups of 8

    const float* A = s1 + ((size_t)b * 1024 + i0) * 128;
    const float* B = s2 + ((size_t)b * 1024 + j0) * 128;

    // acc2[ur][v]: .lo = dot(row ty*8+2ur,   col tx*4+v)
    //              .hi = dot(row ty*8+2ur+1, col tx*4+v)
    unsigned long long acc2[4][4];
#pragma unroll
    for (int ur = 0; ur < 4; ur++)
#pragma unroll
        for (int v = 0; v < 4; v++) acc2[ur][v] = 0ULL;

    for (int kc0 = 0; kc0 < 128; kc0 += 32) {
        __syncthreads();
        // A chunk: 128 rows x 32 k = 4096 elems, transposed
#pragma unroll
        for (int it = 0; it < 16; it++) {
            int e = tid + it * 256;
            int r = e >> 5, c = e & 31;
            asT[c * 132 + r] = A[r * 128 + kc0 + c];
        }
        // B chunk: 64 rows x 32 k, duplicated + swizzled
#pragma unroll
        for (int it = 0; it < 8; it++) {
            int e = tid + it * 256;
            int r = e >> 5, c = e & 31;          // r = local j
            float v = B[r * 128 + kc0 + c];
            int pos = ((r & 3) * 16 + (r >> 2)) * 2;
            bsD[c * 132 + pos] = v;
            bsD[c * 132 + pos + 1] = v;
        }
        __syncthreads();
#pragma unroll
        for (int k = 0; k < 32; k++) {
            unsigned long long av[4], bv[4];
#pragma unroll
            for (int ur = 0; ur < 4; ur++)
                av[ur] = *(const unsigned long long*)&asT[k * 132 + ty * 8 + 2 * ur];
#pragma unroll
            for (int v = 0; v < 4; v++)
                bv[v] = *(const unsigned long long*)&bsD[k * 132 + (v * 16 + tx) * 2];
#pragma unroll
            for (int ur = 0; ur < 4; ur++)
#pragma unroll
                for (int v = 0; v < 4; v++)
                    asm("fma.rn.f32x2 %0, %1, %2, %0;"
                        : "+l"(acc2[ur][v]) : "l"(av[ur]), "l"(bv[v]));
        }
    }
    __syncthreads();

    // Epilogue into staging buffer Ss[128][66] (diagonal read stride 65 -> conflict-free)
    float* Ss = smem;
#pragma unroll
    for (int ur = 0; ur < 4; ur++) {
        int r0 = ty * 8 + 2 * ur;
        float n1a = g_n1[b * 1024 + i0 + r0];
        float n1b = g_n1[b * 1024 + i0 + r0 + 1];
#pragma unroll
        for (int v = 0; v < 4; v++) {
            float n2 = g_n2[b * 1024 + j0 + tx * 4 + v];
            float lo = __uint_as_float((unsigned)(acc2[ur][v] & 0xffffffffULL));
            float hi = __uint_as_float((unsigned)(acc2[ur][v] >> 32));
            float d2a = n1a + n2 - 2.0f * lo;
            float d2b = n1b + n2 - 2.0f * hi;
            Ss[r0 * 66 + tx * 4 + v] = sqrtf(fmaxf(d2a, 0.0f));
            Ss[(r0 + 1) * 66 + tx * 4 + v] = sqrtf(fmaxf(d2b, 0.0f));
        }
    }
    __syncthreads();

    // Diagonal write-out: local diagonals d = li + lj in [0,190], global kc = i0+j0+d.
    int lane = tid & 31;
    int w8 = tid >> 5;
    for (int d = w8; d < 191; d += 8) {
        int lo = d > 63 ? d - 63 : 0;
        int hi = d < 127 ? d : 127;
        size_t base = ((size_t)b * 2048 + (size_t)(i0 + j0 + d)) * 1024 + i0;
        for (int li = lo + lane; li <= hi; li += 32)
            g_Cdiag[base + li] = Ss[li * 66 + (d - li)];
    }
}

// ---------------------------------------------------------------------------
// Kernel 2: DTW wavefront, warp-skewed intervals. 256 threads, thread t owns
// DP rows 4t+1..4t+4 as a register chain. Warp w lags warp w-1 by 16 diags;
// each interval processes 16 diagonals with ONE __syncthreads. Warp-boundary
// values are exchanged via a parity-double-buffered shared edge[2][8][16]:
// producer (lane 31, warp w) writes interval m's 16 values to edge[m&1][w+1],
// consumer (lane 0, warp w+1) reads them in interval m+1. Intra-warp boundary
// is a per-step shfl_up. 16-deep float4 prefetch ring hides cost-read latency
// (one interval ahead ~650 cyc > DRAM ~400).
// ---------------------------------------------------------------------------
__global__ __launch_bounds__(256) void dtw_kernel(float* __restrict__ out) {
    int b = blockIdx.x;
    int t = threadIdx.x;
    int lane = t & 31;
    int w = t >> 5;  // 8 warps

    __shared__ float edge[2][8][16];

    const float4* Cb4 = (const float4*)(g_Cdiag + (size_t)b * 2048 * 1024);
    // diag kc, thread t -> Cb4[kc*256 + t] = C rows 4t..4t+3 on that diagonal

    float prev[4], prev2[4];
#pragma unroll
    for (int r = 0; r < 4; r++) { prev[r] = BIGF; prev2[r] = BIGF; }

    float4 cb[16];
#pragma unroll
    for (int q = 0; q < 16; q++) cb[q] = Cb4[q * 256 + t];

    int i0 = 4 * t + 1;  // first DP row owned by this thread

    for (int m = 0; m < 135; ++m) {
        int mb = m - w;                 // this warp's local interval index
        if (mb >= 0 && mb < 128) {
            float eup[16];
            if (w > 0) {
#pragma unroll
                for (int u = 0; u < 16; u++) eup[u] = edge[(m - 1) & 1][w][u];
            }
#pragma unroll
            for (int u = 0; u < 16; u++) {
                int k = 2 + mb * 16 + u;    // k = 2..2049
                float4 cv = cb[u];
                int pf = mb * 16 + u + 16;
                if (pf > 2047) pf = 2047;
                cb[u] = Cb4[(size_t)pf * 256 + t];

                float nm0 = fminf(prev[0], prev2[0]);
                float nm1 = fminf(prev[1], prev2[1]);
                float nm2 = fminf(prev[2], prev2[2]);
                float nm3 = fminf(prev[3], prev2[3]);

                // publish boundary for next warp (consumed next interval)
                if (lane == 31 && w < 7) edge[m & 1][w + 1][u] = nm3;

                float handoff = __shfl_up_sync(0xffffffffu, nm3, 1);
                float up0 = handoff;
                if (lane == 0)
                    up0 = (w == 0) ? ((k == 2) ? 0.0f : BIGF) : eup[u];

                float c0 = cv.x + fminf(prev[0], up0);
                float c1 = cv.y + fminf(prev[1], nm0);
                float c2 = cv.z + fminf(prev[2], nm1);
                float c3 = cv.w + fminf(prev[3], nm2);

                bool v0 = (k >= i0 + 1) && (k <= i0 + 1024);
                bool v1 = (k >= i0 + 2) && (k <= i0 + 1025);
                bool v2 = (k >= i0 + 3) && (k <= i0 + 1026);
                bool v3 = (k >= i0 + 4) && (k <= i0 + 1027);

                prev2[0] = prev[0]; prev[0] = v0 ? c0 : BIGF;
                prev2[1] = prev[1]; prev[1] = v1 ? c1 : BIGF;
                prev2[2] = prev[2]; prev[2] = v2 ? c2 : BIGF;
                prev2[3] = prev[3]; prev[3] = v3 ? c3 : BIGF;
            }
        }
        __syncthreads();
    }

    if (t == 255) {
        // After k=2049, prev2[3] = D[1024][1024] (set at k=2048).
        // softmax over a single weight == 1 exactly.
        float dist = prev2[3] * (1.0f / 2048.0f);
        out[b] = 1.0f / (1.0f + dist);
    }
}

// ---------------------------------------------------------------------------
extern "C" void kernel_launch(void* const* d_in, const int* in_sizes, int n_in,
                              void* d_out, int out_size) {
    const float* seq1 = (const float*)d_in[0];
    const float* seq2 = (const float*)d_in[1];
    // d_in[2] = scale_weights (1 elem): softmax of a single weight is exactly 1.0.
    float* out = (float*)d_out;

    dim3 gN(128, 32, 2);
    norms_kernel<<<gN, 256>>>(seq1, seq2);

    dim3 gC(16, 8, 32);
    cost_kernel<<<gC, 256>>>(seq1, seq2);

    dtw_kernel<<<32, 256>>>(out);
}

// round 5
// speedup vs baseline: 1.9025x; 1.1548x over previous
#include <cuda_runtime.h>
#include <cuda_fp16.h>
#include <math.h>

#define BIGF 1000000000.0f

// Cost matrix, fp16, anti-diagonal layout CdiagH[b][kc][i], kc=i+j in [0,2046],
// padded to 2048 diagonals. 32*2048*1024 halves = 128 MB. Zero-initialized;
// out-of-band entries are never written and stay 0.0h (dtw relies on this).
static __device__ __align__(256) __half g_CdiagH[67108864];

// ---------------------------------------------------------------------------
// Kernel 1: cost matrix via packed f32x2 FFMA. grid (16, 8, 32).
// Tile = 128(i) x 64(j), 256 thr, 8x4 per thread. Row norms are fused into the
// mainloop (8 extra FFMA2/k on already-loaded operands) - no norms kernel.
// Epilogue: sqrt(max(n1+n2-2dot,0)) -> fp16, staged in shared, written out in
// anti-diagonal-major layout (coalesced diagonal segments).
// ---------------------------------------------------------------------------
__global__ __launch_bounds__(256) void cost_kernel(const float* __restrict__ s1,
                                                   const float* __restrict__ s2) {
    __shared__ float smem[8448];   // asT[32][132] + bsD[32][132]; reused as Ss(half)[128][131]
    float* asT = smem;
    float* bsD = smem + 4224;

    int b = blockIdx.z;
    int i0 = blockIdx.y * 128;
    int j0 = blockIdx.x * 64;
    int tid = threadIdx.x;
    int tx = tid & 15;   // j groups of 4
    int ty = tid >> 4;   // i groups of 8

    const float* A = s1 + ((size_t)b * 1024 + i0) * 128;
    const float* B = s2 + ((size_t)b * 1024 + j0) * 128;

    // acc2[ur][v]: .lo = dot(row ty*8+2ur, col tx*4+v), .hi = same for row+1
    unsigned long long acc2[4][4];
    unsigned long long nA[4];   // (norm(row 2ur), norm(row 2ur+1)) pairs
    unsigned long long nB[4];   // (norm(col v), norm(col v)) dup pairs
#pragma unroll
    for (int ur = 0; ur < 4; ur++) {
        nA[ur] = 0ULL; nB[ur] = 0ULL;
#pragma unroll
        for (int v = 0; v < 4; v++) acc2[ur][v] = 0ULL;
    }

    for (int kc0 = 0; kc0 < 128; kc0 += 32) {
        __syncthreads();
        // A chunk: 128 rows x 32 k, transposed
#pragma unroll
        for (int it = 0; it < 16; it++) {
            int e = tid + it * 256;
            int r = e >> 5, c = e & 31;
            asT[c * 132 + r] = A[r * 128 + kc0 + c];
        }
        // B chunk: 64 rows x 32 k, duplicated + swizzled
#pragma unroll
        for (int it = 0; it < 8; it++) {
            int e = tid + it * 256;
            int r = e >> 5, c = e & 31;          // r = local j
            float v = B[r * 128 + kc0 + c];
            int pos = ((r & 3) * 16 + (r >> 2)) * 2;
            bsD[c * 132 + pos] = v;
            bsD[c * 132 + pos + 1] = v;
        }
        __syncthreads();
#pragma unroll
        for (int k = 0; k < 32; k++) {
            unsigned long long av[4], bv[4];
#pragma unroll
            for (int ur = 0; ur < 4; ur++)
                av[ur] = *(const unsigned long long*)&asT[k * 132 + ty * 8 + 2 * ur];
#pragma unroll
            for (int v = 0; v < 4; v++)
                bv[v] = *(const unsigned long long*)&bsD[k * 132 + (v * 16 + tx) * 2];
#pragma unroll
            for (int ur = 0; ur < 4; ur++) {
                asm("fma.rn.f32x2 %0, %1, %1, %0;" : "+l"(nA[ur]) : "l"(av[ur]));
                asm("fma.rn.f32x2 %0, %1, %1, %0;" : "+l"(nB[ur]) : "l"(bv[ur]));
#pragma unroll
                for (int v = 0; v < 4; v++)
                    asm("fma.rn.f32x2 %0, %1, %2, %0;"
                        : "+l"(acc2[ur][v]) : "l"(av[ur]), "l"(bv[v]));
            }
        }
    }
    __syncthreads();

    // Epilogue: fp16 distances into staging buffer Ss[128][131]
    // (diagonal read stride 130 halves = 65 words -> conflict-free).
    __half* Ss = (__half*)smem;
#pragma unroll
    for (int ur = 0; ur < 4; ur++) {
        int r0 = ty * 8 + 2 * ur;
        float n1a = __uint_as_float((unsigned)(nA[ur] & 0xffffffffULL));
        float n1b = __uint_as_float((unsigned)(nA[ur] >> 32));
#pragma unroll
        for (int v = 0; v < 4; v++) {
            float n2 = __uint_as_float((unsigned)(nB[v] & 0xffffffffULL));
            float lo = __uint_as_float((unsigned)(acc2[ur][v] & 0xffffffffULL));
            float hi = __uint_as_float((unsigned)(acc2[ur][v] >> 32));
            float d2a = n1a + n2 - 2.0f * lo;
            float d2b = n1b + n2 - 2.0f * hi;
            Ss[r0 * 131 + tx * 4 + v] = __float2half_rn(sqrtf(fmaxf(d2a, 0.0f)));
            Ss[(r0 + 1) * 131 + tx * 4 + v] = __float2half_rn(sqrtf(fmaxf(d2b, 0.0f)));
        }
    }
    __syncthreads();

    // Diagonal write-out: local diagonals d = li + lj in [0,190], global kc = i0+j0+d.
    int lane = tid & 31;
    int w8 = tid >> 5;
    for (int d = w8; d < 191; d += 8) {
        int lo = d > 63 ? d - 63 : 0;
        int hi = d < 127 ? d : 127;
        size_t base = ((size_t)b * 2048 + (size_t)(i0 + j0 + d)) * 1024 + i0;
        for (int li = lo + lane; li <= hi; li += 32)
            g_CdiagH[base + li] = Ss[li * 131 + (d - li)];
    }
}

// ---------------------------------------------------------------------------
// Kernel 2: DTW wavefront, warp-skewed 32-step intervals, maskless.
// 256 threads/CTA, thread t owns DP rows 4t+1..4t+4 as a register chain.
// Warp w lags warp w-1 by 32 diagonals; ONE __syncthreads per 32 diagonals.
// Out-of-band cost entries are 0.0h (zero-init, never written), so invalid
// cells compute 0 + BIGF-propagated values and never corrupt valid cells
// (j<=0 cells stay BIGF by induction; j>=1025 cells are finite but can only
// feed cells with even larger j, never re-entering the valid region).
// 32-deep uint2 (4xfp16) prefetch ring hides the streaming cost read.
// ---------------------------------------------------------------------------
__global__ __launch_bounds__(256) void dtw_kernel(float* __restrict__ out) {
    int b = blockIdx.x;
    int t = threadIdx.x;
    int lane = t & 31;
    int w = t >> 5;  // 8 warps

    __shared__ float edge[2][8][32];

    const uint2* CbH = (const uint2*)(g_CdiagH + (size_t)b * 2048 * 1024);
    // diag kc, thread t -> CbH[kc*256 + t] = fp16 cost rows 4t..4t+3 on that diag

    float prev[4], prev2[4];
#pragma unroll
    for (int r = 0; r < 4; r++) { prev[r] = BIGF; prev2[r] = BIGF; }

    uint2 cb[32];
#pragma unroll
    for (int q = 0; q < 32; q++) cb[q] = __ldcs(&CbH[q * 256 + t]);

    for (int m = 0; m < 71; ++m) {
        int mb = m - w;                 // this warp's local interval index
        if (mb >= 0 && mb < 64) {
#pragma unroll
            for (int u = 0; u < 32; ++u) {
                int k = 2 + mb * 32 + u;    // k = 2..2049
                uint2 cw = cb[u];
                int pf = mb * 32 + u + 32;
                if (pf > 2047) pf = 2047;
                cb[u] = __ldcs(&CbH[(size_t)pf * 256 + t]);

                float2 f01 = __half22float2(*reinterpret_cast<__half2*>(&cw.x));
                float2 f23 = __half22float2(*reinterpret_cast<__half2*>(&cw.y));

                float nm0 = fminf(prev[0], prev2[0]);
                float nm1 = fminf(prev[1], prev2[1]);
                float nm2 = fminf(prev[2], prev2[2]);
                float nm3 = fminf(prev[3], prev2[3]);

                // publish boundary for next warp (consumed next global interval)
                if (lane == 31 && w < 7) edge[m & 1][w + 1][u] = nm3;

                float eupv = edge[(m - 1) & 1][w][u];
                float handoff = __shfl_up_sync(0xffffffffu, nm3, 1);
                float up0 = handoff;
                if (lane == 0)
                    up0 = (w == 0) ? ((k == 2) ? 0.0f : BIGF) : eupv;

                float c0 = f01.x + fminf(prev[0], up0);
                float c1 = f01.y + fminf(prev[1], nm0);
                float c2 = f23.x + fminf(prev[2], nm1);
                float c3 = f23.y + fminf(prev[3], nm2);

                prev2[0] = prev[0]; prev[0] = c0;
                prev2[1] = prev[1]; prev[1] = c1;
                prev2[2] = prev[2]; prev[2] = c2;
                prev2[3] = prev[3]; prev[3] = c3;
            }
        }
        __syncthreads();
    }

    if (t == 255) {
        // After k=2049, prev2[3] = D[1024][1024] (set at k=2048).
        // softmax over a single weight == 1 exactly.
        float dist = prev2[3] * (1.0f / 2048.0f);
        out[b] = 1.0f / (1.0f + dist);
    }
}

// ---------------------------------------------------------------------------
extern "C" void kernel_launch(void* const* d_in, const int* in_sizes, int n_in,
                              void* d_out, int out_size) {
    const float* seq1 = (const float*)d_in[0];
    const float* seq2 = (const float*)d_in[1];
    // d_in[2] = scale_weights (1 elem): softmax of a single weight is exactly 1.0.
    float* out = (float*)d_out;

    dim3 gC(16, 8, 32);
    cost_kernel<<<gC, 256>>>(seq1, seq2);

    dtw_kernel<<<32, 256>>>(out);
}

// round 6
// speedup vs baseline: 3.3334x; 1.7521x over previous
#include <cuda_runtime.h>
#include <cuda_fp16.h>
#include <math.h>

#define BIGF 1000000000.0f

// Cost matrix, fp16, anti-diagonal layout CdiagH[b][kc][i], kc=i+j in [0,2046],
// padded to 2048 diagonals. 32*2048*1024 halves = 128 MB. Zero-initialized;
// out-of-band entries are never written and stay 0.0h (dtw relies on this).
static __device__ __align__(256) __half g_CdiagH[67108864];
static __device__ float g_n1[32 * 1024];
static __device__ float g_n2[32 * 1024];

// ---------------------------------------------------------------------------
// Kernel 0: row squared norms (fp32, from raw inputs). One warp per row.
// ---------------------------------------------------------------------------
__global__ __launch_bounds__(256) void norms_kernel(const float* __restrict__ s1,
                                                    const float* __restrict__ s2) {
    int b = blockIdx.y;
    const float* s = blockIdx.z ? s2 : s1;
    float* o = blockIdx.z ? g_n2 : g_n1;
    int lane = threadIdx.x & 31;
    int wid = threadIdx.x >> 5;
    int r = blockIdx.x * 8 + wid;
    const float4* p = (const float4*)(s + ((size_t)b * 1024 + r) * 128);
    float4 v = p[lane];
    float acc = v.x * v.x + v.y * v.y + v.z * v.z + v.w * v.w;
#pragma unroll
    for (int off = 16; off; off >>= 1)
        acc += __shfl_xor_sync(0xffffffffu, acc, off);
    if (lane == 0) o[b * 1024 + r] = acc;
}

// ---------------------------------------------------------------------------
// Kernel 1: cost matrix via tf32 tensor-core mma.sync.m16n8k8.
// grid (8, 8, 32) = (j-tile, i-tile, batch); CTA tile 128(i) x 128(j).
// 8 warps in 2(m) x 4(n) grid, warp tile 64x32 -> 4x4 mma tiles, 64 accum regs.
// K staged in 32-wide chunks, stored tf32-rounded in padded smem (stride 36:
// fragment loads land on distinct banks). Epilogue sqrt(max(n1+n2-2dot,0))
// -> fp16, staged in shared (stride 131: diagonal reads conflict-free), then
// written out in anti-diagonal-major layout.
// ---------------------------------------------------------------------------
#define MMA_TF32(C0, C1, C2, C3, A0, A1, A2, A3, B0, B1)                      \
    asm volatile(                                                              \
        "mma.sync.aligned.m16n8k8.row.col.f32.tf32.tf32.f32 "                  \
        "{%0,%1,%2,%3}, {%4,%5,%6,%7}, {%8,%9}, {%0,%1,%2,%3};"                \
        : "+f"(C0), "+f"(C1), "+f"(C2), "+f"(C3)                               \
        : "r"(A0), "r"(A1), "r"(A2), "r"(A3), "r"(B0), "r"(B1))

__device__ __forceinline__ float to_tf32(float x) {
    float y;
    asm("cvt.rna.tf32.f32 %0, %1;" : "=f"(y) : "f"(x));
    return y;
}

__global__ __launch_bounds__(256) void cost_kernel(const float* __restrict__ s1,
                                                   const float* __restrict__ s2) {
    __shared__ float smem[9216];       // asmem[128][36] + bsmem[128][36]; reused as Ss(half)[128][131]
    float* asmem = smem;               // [i][k] tf32-rounded
    float* bsmem = smem + 4608;        // [j][k] tf32-rounded

    int b = blockIdx.z;
    int i0 = blockIdx.y * 128;
    int j0 = blockIdx.x * 128;
    int tid = threadIdx.x;
    int lane = tid & 31;
    int w = tid >> 5;
    int wm = w >> 2;          // 0..1  (m)
    int wn = w & 3;           // 0..3  (n)
    int g = lane >> 2;        // groupID 0..7
    int tg = lane & 3;        // threadID_in_group 0..3

    const float* A = s1 + ((size_t)b * 1024 + i0) * 128;
    const float* B = s2 + ((size_t)b * 1024 + j0) * 128;

    float c[4][4][4];
#pragma unroll
    for (int mt = 0; mt < 4; mt++)
#pragma unroll
        for (int nt = 0; nt < 4; nt++)
#pragma unroll
            for (int q = 0; q < 4; q++) c[mt][nt][q] = 0.0f;

    for (int kc0 = 0; kc0 < 128; kc0 += 32) {
        __syncthreads();
        // Stage A,B chunks (128 rows x 32 k each) as tf32, float4 loads/stores.
#pragma unroll
        for (int it = 0; it < 4; it++) {
            int u = tid + it * 256;          // 1024 float4 units
            int r = u >> 3;
            int c0 = (u & 7) * 4;
            float4 va = *(const float4*)&A[r * 128 + kc0 + c0];
            va.x = to_tf32(va.x); va.y = to_tf32(va.y);
            va.z = to_tf32(va.z); va.w = to_tf32(va.w);
            *(float4*)&asmem[r * 36 + c0] = va;
            float4 vb = *(const float4*)&B[r * 128 + kc0 + c0];
            vb.x = to_tf32(vb.x); vb.y = to_tf32(vb.y);
            vb.z = to_tf32(vb.z); vb.w = to_tf32(vb.w);
            *(float4*)&bsmem[r * 36 + c0] = vb;
        }
        __syncthreads();

#pragma unroll
        for (int ks = 0; ks < 4; ks++) {
            unsigned af[4][4], bf[4][2];
#pragma unroll
            for (int mt = 0; mt < 4; mt++) {
                int ar = wm * 64 + mt * 16;
                af[mt][0] = __float_as_uint(asmem[(ar + g) * 36 + ks * 8 + tg]);
                af[mt][1] = __float_as_uint(asmem[(ar + 8 + g) * 36 + ks * 8 + tg]);
                af[mt][2] = __float_as_uint(asmem[(ar + g) * 36 + ks * 8 + tg + 4]);
                af[mt][3] = __float_as_uint(asmem[(ar + 8 + g) * 36 + ks * 8 + tg + 4]);
            }
#pragma unroll
            for (int nt = 0; nt < 4; nt++) {
                int br = wn * 32 + nt * 8;
                bf[nt][0] = __float_as_uint(bsmem[(br + g) * 36 + ks * 8 + tg]);
                bf[nt][1] = __float_as_uint(bsmem[(br + g) * 36 + ks * 8 + tg + 4]);
            }
#pragma unroll
            for (int mt = 0; mt < 4; mt++)
#pragma unroll
                for (int nt = 0; nt < 4; nt++)
                    MMA_TF32(c[mt][nt][0], c[mt][nt][1], c[mt][nt][2], c[mt][nt][3],
                             af[mt][0], af[mt][1], af[mt][2], af[mt][3],
                             bf[nt][0], bf[nt][1]);
        }
    }
    __syncthreads();

    // Epilogue: fp16 distances into staging buffer Ss[128][131]
    // (diagonal read step = 130 halves = 65 words -> conflict-free).
    __half* Ss = (__half*)smem;
#pragma unroll
    for (int mt = 0; mt < 4; mt++) {
        int r0 = wm * 64 + mt * 16 + g;     // rows r0 and r0+8
        float n1a = g_n1[b * 1024 + i0 + r0];
        float n1b = g_n1[b * 1024 + i0 + r0 + 8];
#pragma unroll
        for (int nt = 0; nt < 4; nt++) {
            int c0 = wn * 32 + nt * 8 + 2 * tg;   // cols c0, c0+1
            float n2a = g_n2[b * 1024 + j0 + c0];
            float n2b = g_n2[b * 1024 + j0 + c0 + 1];
            float d00 = n1a + n2a - 2.0f * c[mt][nt][0];
            float d01 = n1a + n2b - 2.0f * c[mt][nt][1];
            float d10 = n1b + n2a - 2.0f * c[mt][nt][2];
            float d11 = n1b + n2b - 2.0f * c[mt][nt][3];
            Ss[r0 * 131 + c0]           = __float2half_rn(sqrtf(fmaxf(d00, 0.0f)));
            Ss[r0 * 131 + c0 + 1]       = __float2half_rn(sqrtf(fmaxf(d01, 0.0f)));
            Ss[(r0 + 8) * 131 + c0]     = __float2half_rn(sqrtf(fmaxf(d10, 0.0f)));
            Ss[(r0 + 8) * 131 + c0 + 1] = __float2half_rn(sqrtf(fmaxf(d11, 0.0f)));
        }
    }
    __syncthreads();

    // Diagonal write-out: local diagonals d = li + lj in [0,254], global kc = i0+j0+d.
    for (int d = w; d < 255; d += 8) {
        int lo = d > 127 ? d - 127 : 0;
        int hi = d < 127 ? d : 127;
        size_t base = ((size_t)b * 2048 + (size_t)(i0 + j0 + d)) * 1024 + i0;
        for (int li = lo + lane; li <= hi; li += 32)
            g_CdiagH[base + li] = Ss[li * 131 + (d - li)];
    }
}

// ---------------------------------------------------------------------------
// Kernel 2: DTW wavefront, warp-skewed 32-step intervals, maskless (unchanged).
// ---------------------------------------------------------------------------
__global__ __launch_bounds__(256) void dtw_kernel(float* __restrict__ out) {
    int b = blockIdx.x;
    int t = threadIdx.x;
    int lane = t & 31;
    int w = t >> 5;  // 8 warps

    __shared__ float edge[2][8][32];

    const uint2* CbH = (const uint2*)(g_CdiagH + (size_t)b * 2048 * 1024);

    float prev[4], prev2[4];
#pragma unroll
    for (int r = 0; r < 4; r++) { prev[r] = BIGF; prev2[r] = BIGF; }

    uint2 cb[32];
#pragma unroll
    for (int q = 0; q < 32; q++) cb[q] = __ldcs(&CbH[q * 256 + t]);

    for (int m = 0; m < 71; ++m) {
        int mb = m - w;
        if (mb >= 0 && mb < 64) {
#pragma unroll
            for (int u = 0; u < 32; ++u) {
                int k = 2 + mb * 32 + u;    // k = 2..2049
                uint2 cw = cb[u];
                int pf = mb * 32 + u + 32;
                if (pf > 2047) pf = 2047;
                cb[u] = __ldcs(&CbH[(size_t)pf * 256 + t]);

                float2 f01 = __half22float2(*reinterpret_cast<__half2*>(&cw.x));
                float2 f23 = __half22float2(*reinterpret_cast<__half2*>(&cw.y));

                float nm0 = fminf(prev[0], prev2[0]);
                float nm1 = fminf(prev[1], prev2[1]);
                float nm2 = fminf(prev[2], prev2[2]);
                float nm3 = fminf(prev[3], prev2[3]);

                if (lane == 31 && w < 7) edge[m & 1][w + 1][u] = nm3;

                float eupv = edge[(m - 1) & 1][w][u];
                float handoff = __shfl_up_sync(0xffffffffu, nm3, 1);
                float up0 = handoff;
                if (lane == 0)
                    up0 = (w == 0) ? ((k == 2) ? 0.0f : BIGF) : eupv;

                float c0 = f01.x + fminf(prev[0], up0);
                float c1 = f01.y + fminf(prev[1], nm0);
                float c2 = f23.x + fminf(prev[2], nm1);
                float c3 = f23.y + fminf(prev[3], nm2);

                prev2[0] = prev[0]; prev[0] = c0;
                prev2[1] = prev[1]; prev[1] = c1;
                prev2[2] = prev[2]; prev[2] = c2;
                prev2[3] = prev[3]; prev[3] = c3;
            }
        }
        __syncthreads();
    }

    if (t == 255) {
        float dist = prev2[3] * (1.0f / 2048.0f);
        out[b] = 1.0f / (1.0f + dist);
    }
}

// ---------------------------------------------------------------------------
extern "C" void kernel_launch(void* const* d_in, const int* in_sizes, int n_in,
                              void* d_out, int out_size) {
    const float* seq1 = (const float*)d_in[0];
    const float* seq2 = (const float*)d_in[1];
    // d_in[2] = scale_weights (1 elem): softmax of a single weight is exactly 1.0.
    float* out = (float*)d_out;

    dim3 gN(128, 32, 2);
    norms_kernel<<<gN, 256>>>(seq1, seq2);

    dim3 gC(8, 8, 32);
    cost_kernel<<<gC, 256>>>(seq1, seq2);

    dtw_kernel<<<32, 256>>>(out);
}

// round 7
// speedup vs baseline: 3.5979x; 1.0793x over previous
#include <cuda_runtime.h>
#include <cuda_fp16.h>
#include <math.h>

#define BIGF 1000000000.0f

// Cost matrix, fp16, SKEWED anti-diagonal layout:
// slot(b, sigma, t) holds costs of DP rows 4t+1..4t+4 at diagonal kc = sigma - (t&31),
// stored as 4 halves at halves-address ((b*2144 + sigma)*1024 + 4t .. +3).
// sigma in [0, 2143] (2077 used + prefetch pad). Zero-initialized; slots with
// kc out of [0,2046] or out-of-band cells are never written and stay 0.0h.
static __device__ __align__(256) __half g_CH[70254592];   // 32*2144*1024
static __device__ float g_n1[32 * 1024];
static __device__ float g_n2[32 * 1024];

// ---------------------------------------------------------------------------
// Kernel 0: row squared norms (fp32, from raw inputs). One warp per row.
// ---------------------------------------------------------------------------
__global__ __launch_bounds__(256) void norms_kernel(const float* __restrict__ s1,
                                                    const float* __restrict__ s2) {
    int b = blockIdx.y;
    const float* s = blockIdx.z ? s2 : s1;
    float* o = blockIdx.z ? g_n2 : g_n1;
    int lane = threadIdx.x & 31;
    int wid = threadIdx.x >> 5;
    int r = blockIdx.x * 8 + wid;
    const float4* p = (const float4*)(s + ((size_t)b * 1024 + r) * 128);
    float4 v = p[lane];
    float acc = v.x * v.x + v.y * v.y + v.z * v.z + v.w * v.w;
#pragma unroll
    for (int off = 16; off; off >>= 1)
        acc += __shfl_xor_sync(0xffffffffu, acc, off);
    if (lane == 0) o[b * 1024 + r] = acc;
}

// ---------------------------------------------------------------------------
// Kernel 1: cost matrix via tf32 tensor-core mma.sync.m16n8k8 (as R6).
// grid (8, 8, 32); CTA tile 128(i) x 128(j); 8 warps 2x4; warp tile 64x32.
// Epilogue sqrt(max(n1+n2-2dot,0)) -> fp16 staged in shared (stride 131),
// then written out in the SKEWED sigma-layout: for cell (r=i-1, kc):
//   sigma = kc + ((r>>2)&31);  halves_addr = (b*2144 + sigma)*1024 + r.
// For fixed sigma the 128 rows of the tile are CONTIGUOUS halves -> coalesced.
// ---------------------------------------------------------------------------
#define MMA_TF32(C0, C1, C2, C3, A0, A1, A2, A3, B0, B1)                      \
    asm volatile(                                                              \
        "mma.sync.aligned.m16n8k8.row.col.f32.tf32.tf32.f32 "                  \
        "{%0,%1,%2,%3}, {%4,%5,%6,%7}, {%8,%9}, {%0,%1,%2,%3};"                \
        : "+f"(C0), "+f"(C1), "+f"(C2), "+f"(C3)                               \
        : "r"(A0), "r"(A1), "r"(A2), "r"(A3), "r"(B0), "r"(B1))

__device__ __forceinline__ float to_tf32(float x) {
    float y;
    asm("cvt.rna.tf32.f32 %0, %1;" : "=f"(y) : "f"(x));
    return y;
}

__global__ __launch_bounds__(256) void cost_kernel(const float* __restrict__ s1,
                                                   const float* __restrict__ s2) {
    __shared__ float smem[9216];       // asmem[128][36] + bsmem[128][36]; reused as Ss(half)[128][131]
    float* asmem = smem;
    float* bsmem = smem + 4608;

    int b = blockIdx.z;
    int i0 = blockIdx.y * 128;
    int j0 = blockIdx.x * 128;
    int tid = threadIdx.x;
    int lane = tid & 31;
    int w = tid >> 5;
    int wm = w >> 2;
    int wn = w & 3;
    int g = lane >> 2;
    int tg = lane & 3;

    const float* A = s1 + ((size_t)b * 1024 + i0) * 128;
    const float* B = s2 + ((size_t)b * 1024 + j0) * 128;

    float c[4][4][4];
#pragma unroll
    for (int mt = 0; mt < 4; mt++)
#pragma unroll
        for (int nt = 0; nt < 4; nt++)
#pragma unroll
            for (int q = 0; q < 4; q++) c[mt][nt][q] = 0.0f;

    for (int kc0 = 0; kc0 < 128; kc0 += 32) {
        __syncthreads();
#pragma unroll
        for (int it = 0; it < 4; it++) {
            int u = tid + it * 256;
            int r = u >> 3;
            int c0 = (u & 7) * 4;
            float4 va = *(const float4*)&A[r * 128 + kc0 + c0];
            va.x = to_tf32(va.x); va.y = to_tf32(va.y);
            va.z = to_tf32(va.z); va.w = to_tf32(va.w);
            *(float4*)&asmem[r * 36 + c0] = va;
            float4 vb = *(const float4*)&B[r * 128 + kc0 + c0];
            vb.x = to_tf32(vb.x); vb.y = to_tf32(vb.y);
            vb.z = to_tf32(vb.z); vb.w = to_tf32(vb.w);
            *(float4*)&bsmem[r * 36 + c0] = vb;
        }
        __syncthreads();

#pragma unroll
        for (int ks = 0; ks < 4; ks++) {
            unsigned af[4][4], bf[4][2];
#pragma unroll
            for (int mt = 0; mt < 4; mt++) {
                int ar = wm * 64 + mt * 16;
                af[mt][0] = __float_as_uint(asmem[(ar + g) * 36 + ks * 8 + tg]);
                af[mt][1] = __float_as_uint(asmem[(ar + 8 + g) * 36 + ks * 8 + tg]);
                af[mt][2] = __float_as_uint(asmem[(ar + g) * 36 + ks * 8 + tg + 4]);
                af[mt][3] = __float_as_uint(asmem[(ar + 8 + g) * 36 + ks * 8 + tg + 4]);
            }
#pragma unroll
            for (int nt = 0; nt < 4; nt++) {
                int br = wn * 32 + nt * 8;
                bf[nt][0] = __float_as_uint(bsmem[(br + g) * 36 + ks * 8 + tg]);
                bf[nt][1] = __float_as_uint(bsmem[(br + g) * 36 + ks * 8 + tg + 4]);
            }
#pragma unroll
            for (int mt = 0; mt < 4; mt++)
#pragma unroll
                for (int nt = 0; nt < 4; nt++)
                    MMA_TF32(c[mt][nt][0], c[mt][nt][1], c[mt][nt][2], c[mt][nt][3],
                             af[mt][0], af[mt][1], af[mt][2], af[mt][3],
                             bf[nt][0], bf[nt][1]);
        }
    }
    __syncthreads();

    // Epilogue: fp16 distances into staging buffer Ss[128][131].
    __half* Ss = (__half*)smem;
#pragma unroll
    for (int mt = 0; mt < 4; mt++) {
        int r0 = wm * 64 + mt * 16 + g;
        float n1a = g_n1[b * 1024 + i0 + r0];
        float n1b = g_n1[b * 1024 + i0 + r0 + 8];
#pragma unroll
        for (int nt = 0; nt < 4; nt++) {
            int c0 = wn * 32 + nt * 8 + 2 * tg;
            float n2a = g_n2[b * 1024 + j0 + c0];
            float n2b = g_n2[b * 1024 + j0 + c0 + 1];
            float d00 = n1a + n2a - 2.0f * c[mt][nt][0];
            float d01 = n1a + n2b - 2.0f * c[mt][nt][1];
            float d10 = n1b + n2a - 2.0f * c[mt][nt][2];
            float d11 = n1b + n2b - 2.0f * c[mt][nt][3];
            Ss[r0 * 131 + c0]           = __float2half_rn(sqrtf(fmaxf(d00, 0.0f)));
            Ss[r0 * 131 + c0 + 1]       = __float2half_rn(sqrtf(fmaxf(d01, 0.0f)));
            Ss[(r0 + 8) * 131 + c0]     = __float2half_rn(sqrtf(fmaxf(d10, 0.0f)));
            Ss[(r0 + 8) * 131 + c0 + 1] = __float2half_rn(sqrtf(fmaxf(d11, 0.0f)));
        }
    }
    __syncthreads();

    // Skewed writeout: sigma_loc = rloc + jloc + (rloc>>2) in [0,285].
    // 256 threads cover 2 sigma values per iteration; rloc = tid&127 gives
    // contiguous halves per sigma -> coalesced 2B stores in 64B warp chunks.
    {
        int rloc = tid & 127;
        int sh = tid >> 7;             // 0 or 1
        int rterm = rloc + (rloc >> 2);
        for (int sl = 0; sl < 286; sl += 2) {
            int sloc = sl + sh;
            int jloc = sloc - rterm;
            if (jloc >= 0 && jloc < 128) {
                size_t addr = ((size_t)b * 2144 + (size_t)(i0 + j0 + sloc)) * 1024
                              + (size_t)(i0 + rloc);
                g_CH[addr] = Ss[rloc * 131 + jloc];
            }
        }
    }
}

// ---------------------------------------------------------------------------
// Kernel 2: DTW wavefront, lane-skewed pipeline. 256 threads, thread t owns
// DP rows 4t+1..4t+4 (register chain). Lane l runs 1 diagonal behind lane l-1:
// lane l at (interval mb, step u) processes diag k = 2 + mb*32 + u - l, reading
// the lane-independent slot sigma = mb*32 + u (coalesced). The shfl_up of nm3
// is issued at step tau and consumed at tau+1 -> its latency is off the
// critical path (which is now fmin+fmin+fadd ~ 12 cyc). Warp w lags warp w-1
// by 2 intervals; boundary values flow through triple-buffered edge[3][8][32],
// hoisted into registers at interval start. Out-of-band/unwritten cost slots
// are 0.0h: BIGF-propagation keeps invalid cells harmless (same induction as
// R5/R6). Answer D[1024][1024] is captured when thread 255 hits k==2048
// (mb=64, u=29), before any drain-phase garbage can reach it.
// ---------------------------------------------------------------------------
__global__ __launch_bounds__(256, 1) void dtw_kernel(float* __restrict__ out) {
    int b = blockIdx.x;
    int t = threadIdx.x;
    int lane = t & 31;
    int w = t >> 5;  // 8 warps

    __shared__ float edge[3][8][32];
    for (int s = t; s < 3 * 8 * 32; s += 256) (&edge[0][0][0])[s] = BIGF;
    __syncthreads();

    const uint2* C = (const uint2*)(g_CH + (size_t)b * 2144 * 1024);
    // slot sigma, thread t -> C[sigma*256 + t] = 4 fp16 costs, rows 4t..4t+3, kc = sigma-lane

    float prev[4], prev2[4];
#pragma unroll
    for (int r = 0; r < 4; r++) { prev[r] = BIGF; prev2[r] = BIGF; }

    uint2 cb[32];
#pragma unroll
    for (int q = 0; q < 32; q++) cb[q] = __ldcs(&C[q * 256 + t]);

    float eup[32];
    float nextup = BIGF;
    float ans = BIGF;

    for (int m = 0; m < 79; ++m) {
        int mb = m - 2 * w;
        if (mb >= 0 && mb <= 64) {
            // Hoist inter-warp boundary values for this interval.
            if (lane == 0) {
                if (w == 0) {
#pragma unroll
                    for (int u = 0; u < 32; u++) eup[u] = BIGF;
                    if (m == 0) eup[0] = 0.0f;      // D[0][0]=0 feeds k==2 only
                } else {
                    eup[0] = edge[(m + 1) % 3][w][31];      // produced at interval m-2
#pragma unroll
                    for (int u = 1; u < 32; u++)
                        eup[u] = edge[(m + 2) % 3][w][u - 1];  // produced at m-1
                }
            }
            int kb = 2 + mb * 32 - lane;                 // k = kb + u
            const uint2* Cbase = C + (size_t)(mb * 32) * 256 + t;
#pragma unroll
            for (int u = 0; u < 32; ++u) {
                uint2 cw = cb[u];
                cb[u] = __ldcs(Cbase + (size_t)(u + 32) * 256);  // sigma+32 <= 2111 < 2144

                float2 f01 = __half22float2(*reinterpret_cast<__half2*>(&cw.x));
                float2 f23 = __half22float2(*reinterpret_cast<__half2*>(&cw.y));

                float up = (lane == 0) ? eup[u] : nextup;   // shfl result from prev step

                float nm0 = fminf(prev[0], prev2[0]);
                float nm1 = fminf(prev[1], prev2[1]);
                float nm2 = fminf(prev[2], prev2[2]);
                float nm3 = fminf(prev[3], prev2[3]);

                nextup = __shfl_up_sync(0xffffffffu, nm3, 1);   // consumed next step
                if (lane == 31 && w < 7) edge[m % 3][w + 1][u] = nm3;

                float c0 = f01.x + fminf(prev[0], up);
                float c1 = f01.y + fminf(prev[1], nm0);
                float c2 = f23.x + fminf(prev[2], nm1);
                float c3 = f23.y + fminf(prev[3], nm2);

                if (kb + u == 2048) ans = c3;   // thread 255: D[1024][1024]

                prev2[0] = prev[0]; prev[0] = c0;
                prev2[1] = prev[1]; prev[1] = c1;
                prev2[2] = prev[2]; prev[2] = c2;
                prev2[3] = prev[3]; prev[3] = c3;
            }
        }
        __syncthreads();
    }

    if (t == 255) {
        // softmax over a single weight == 1 exactly.
        float dist = ans * (1.0f / 2048.0f);
        out[b] = 1.0f / (1.0f + dist);
    }
}

// ---------------------------------------------------------------------------
extern "C" void kernel_launch(void* const* d_in, const int* in_sizes, int n_in,
                              void* d_out, int out_size) {
    const float* seq1 = (const float*)d_in[0];
    const float* seq2 = (const float*)d_in[1];
    // d_in[2] = scale_weights (1 elem): softmax of a single weight is exactly 1.0.
    float* out = (float*)d_out;

    dim3 gN(128, 32, 2);
    norms_kernel<<<gN, 256>>>(seq1, seq2);

    dim3 gC(8, 8, 32);
    cost_kernel<<<gC, 256>>>(seq1, seq2);

    dtw_kernel<<<32, 256>>>(out);
}